// round 6
// baseline (speedup 1.0000x reference)
#include <cuda_runtime.h>

#define TPB    256
#define NBINS  15
#define NCLS   16
#define NCELLS (NBINS * NCLS)   // 240
#define NBLK   1064             // 152 SMs * 7 blocks = exactly one wave

// Per-block per-cell partials, [cell][block] so the tail reads rows contiguously.
__device__ float        g_partials[NCELLS * NBLK];
__device__ unsigned int g_ticket = 0;

__device__ __forceinline__ void proc2(float2 xv, float2 tv,
                                      float* __restrict__ a0,
                                      float* __restrict__ a1) {
    // a0/a1: per-thread column base of plane 0/1, stride TPB floats per bin.
    float p0 = __fdividef(1.0f, 1.0f + __expf(-xv.x));
    float p1 = __fdividef(1.0f, 1.0f + __expf(-xv.y));
    int b0 = (int)(p0 * 15.0f); b0 = b0 > 14 ? 14 : b0;
    int b1 = (int)(p1 * 15.0f); b1 = b1 > 14 ? 14 : b1;
    a0[b0 * TPB] += p0 - tv.x;
    a1[b1 * TPB] += p1 - tv.y;
}

__global__ void __launch_bounds__(TPB, 7)
ece_fused(const float2* __restrict__ x2, const float2* __restrict__ t2, int n2,
          float* __restrict__ out, float inv_scale) {
    // acc[j][bin][tid], j = parity within the float2. class(2i+j) = 2*(i&7)+j
    // is loop-invariant per (thread, j) since the grid stride is a multiple
    // of 8. Lane stride 4B -> conflict-free LDS/STS.
    __shared__ float acc[2][NBINS][TPB];
    const int tid = threadIdx.x;
    #pragma unroll
    for (int b = 0; b < NBINS; b++) { acc[0][b][tid] = 0.0f; acc[1][b][tid] = 0.0f; }
    __syncthreads();

    float* a0 = &acc[0][0][tid];
    float* a1 = &acc[1][0][tid];

    const int stride = NBLK * TPB;
    int i = blockIdx.x * TPB + tid;

    for (; i + 3 * stride < n2; i += 4 * stride) {
        float2 x0 = __ldcs(&x2[i]);
        float2 x1 = __ldcs(&x2[i + stride]);
        float2 x2v = __ldcs(&x2[i + 2 * stride]);
        float2 x3 = __ldcs(&x2[i + 3 * stride]);
        float2 t0 = __ldcs(&t2[i]);
        float2 t1 = __ldcs(&t2[i + stride]);
        float2 t2v = __ldcs(&t2[i + 2 * stride]);
        float2 t3 = __ldcs(&t2[i + 3 * stride]);
        proc2(x0, t0, a0, a1);
        proc2(x1, t1, a0, a1);
        proc2(x2v, t2v, a0, a1);
        proc2(x3, t3, a0, a1);
    }
    for (; i < n2; i += stride) {
        proc2(__ldcs(&x2[i]), __ldcs(&t2[i]), a0, a1);
    }
    __syncthreads();

    // Fold 2*256 private slots into 240 cells. Cell = tid (< 240):
    // bin b = tid>>4, class c = tid&15 = 2q+j -> slots k*8+q, k=0..31.
    if (tid < NCELLS) {
        int b = tid >> 4;
        int c = tid & 15;
        int q = c >> 1;
        int j = c & 1;
        float s = 0.0f;
        #pragma unroll
        for (int k = 0; k < 32; k++) s += acc[j][b][k * 8 + q];
        g_partials[tid * NBLK + blockIdx.x] = s;
    }

    // Last-block tail: reduce the (L2-hot) partials in-kernel.
    __threadfence();
    __shared__ bool isLast;
    if (tid == 0)
        isLast = (atomicAdd(&g_ticket, 1u) == (unsigned)(NBLK - 1));
    __syncthreads();
    if (!isLast) return;

    __shared__ float warp_tot[TPB / 32];
    const int warp = tid >> 5;
    const int lane = tid & 31;
    float total = 0.0f;
    for (int cell = warp; cell < NCELLS; cell += TPB / 32) {
        const float4* row = (const float4*)&g_partials[cell * NBLK];  // 266 float4
        float s0 = 0.0f, s1 = 0.0f, s2 = 0.0f, s3 = 0.0f;
        int k = lane;
        #pragma unroll 8
        for (; k < NBLK / 4; k += 32) {
            float4 v = row[k];
            s0 += v.x; s1 += v.y; s2 += v.z; s3 += v.w;
        }
        float s = (s0 + s1) + (s2 + s3);
        #pragma unroll
        for (int off = 16; off > 0; off >>= 1)
            s += __shfl_xor_sync(0xffffffffu, s, off);
        if (lane == 0) total += fabsf(s);
    }
    if (lane == 0) warp_tot[warp] = total;
    __syncthreads();
    if (tid == 0) {
        float t = 0.0f;
        #pragma unroll
        for (int w = 0; w < TPB / 32; w++) t += warp_tot[w];
        out[0] = t * inv_scale;
        g_ticket = 0;   // reset for next graph replay
    }
}

extern "C" void kernel_launch(void* const* d_in, const int* in_sizes, int n_in,
                              void* d_out, int out_size) {
    const float2* x2 = (const float2*)d_in[0];
    const float2* t2 = (const float2*)d_in[1];
    float* out = (float*)d_out;
    const int n  = in_sizes[0];            // B*C = 33 554 432
    const int n2 = n >> 1;
    const float B = (float)(n / NCLS);

    // ECE = (sum over 240 cells of |sum(p - t)|) / B / NCELLS  (all nonempty)
    ece_fused<<<NBLK, TPB>>>(x2, t2, n2, out, 1.0f / (B * (float)NCELLS));
}